// round 1
// baseline (speedup 1.0000x reference)
#include <cuda_runtime.h>
#include <math.h>

#define B   64
#define T   200
#define Q   4096
#define Q2  (2*Q)
#define TM1 (T-1)          // 199
#define NROW (B*TM1)       // 12736

// Scratch (no device allocation allowed in kernel_launch)
__device__ float g_p[NROW];
__device__ float g_a[NROW];
__device__ int   g_flag[NROW];
__device__ float g_lossb[B];

// ---------------------------------------------------------------------------
// Kernel 1: scan one batch row (b, s=t+1) of 8192 floats, find the one-hot
// index, gather pred[b, t, q]. One block per row, 256 threads, 8x float4 each.
// ---------------------------------------------------------------------------
__global__ __launch_bounds__(256)
void scan_rows_kernel(const float* __restrict__ pred,
                      const float* __restrict__ batch)
{
    const int row = blockIdx.x;        // 0 .. NROW-1
    const int b   = row / TM1;
    const int t   = row % TM1;         // output time index 0..198
    const int s   = t + 1;             // batch row actually read (1..199)

    const float4* __restrict__ base =
        reinterpret_cast<const float4*>(batch + ((size_t)b * T + s) * (size_t)Q2);

    const int tid = threadIdx.x;
    int found = -1;

    // 8192 floats = 2048 float4; 256 threads * 8 vectors, coalesced stride-256.
    #pragma unroll
    for (int k = 0; k < 8; ++k) {
        const int vi = tid + k * 256;
        const float4 v = base[vi];
        if (v.x != 0.0f) found = vi * 4 + 0;
        if (v.y != 0.0f) found = vi * 4 + 1;
        if (v.z != 0.0f) found = vi * 4 + 2;
        if (v.w != 0.0f) found = vi * 4 + 3;
    }

    __shared__ int s_idx;
    if (tid == 0) s_idx = -1;
    __syncthreads();
    if (found >= 0) s_idx = found;     // at most one thread ever finds one
    __syncthreads();

    if (tid == 0) {
        const int j = s_idx;
        float p = 0.0f, a = 0.0f;
        int flag = 0;
        if (j >= 0) {
            const int q = (j < Q) ? j : (j - Q);
            a = (j < Q) ? 1.0f : 0.0f;
            p = __ldg(pred + ((size_t)b * T + t) * (size_t)Q + q);
            flag = 1;
        }
        g_p[row]    = p;
        g_a[row]    = a;
        g_flag[row] = flag;
    }
}

// ---------------------------------------------------------------------------
// Kernel 2: one block per b. Compute last/start/mask/cnt, BCE, write the three
// output arrays, per-b partial loss.
// Output layout: [0]=loss, [1 .. 1+N)=p*maskf, [1+N .. 1+2N)=a*maskf,
//                [1+2N .. 1+3N)=mask (0/1),  N = B*TM1.
// ---------------------------------------------------------------------------
__global__ __launch_bounds__(256)
void per_batch_kernel(const int* __restrict__ isTestP,
                      const int* __restrict__ tslP,
                      float* __restrict__ d_out)
{
    const int b   = blockIdx.x;
    const int tid = threadIdx.x;

    float p = 0.0f, a = 0.0f;
    int myLast = -1;
    if (tid < TM1) {
        const int idx = b * TM1 + tid;
        p = g_p[idx];
        a = g_a[idx];
        if (g_flag[idx] > 0) myLast = tid;
    }

    __shared__ int s_i[256];
    s_i[tid] = myLast;
    __syncthreads();
    #pragma unroll
    for (int off = 128; off > 0; off >>= 1) {
        if (tid < off) s_i[tid] = max(s_i[tid], s_i[tid + off]);
        __syncthreads();
    }
    const int last = max(s_i[0], 0);

    int start = 0;
    const int isTest = *isTestP;
    if (isTest) {
        const int length = last + 1;
        const int tsl = *tslP;
        start = (length > tsl) ? (length - tsl) : 0;
    }

    const bool  m     = (tid < TM1) && (tid >= start) && (tid <= last);
    const float maskf = m ? 1.0f : 0.0f;
    const float cnt   = (float)(last - start + 1);

    float bce = 0.0f;
    if (tid < TM1) {
        const float logp  = fmaxf(logf(p), -100.0f);
        const float l1mp  = fmaxf(log1pf(-p), -100.0f);
        bce = -(a * logp + (1.0f - a) * l1mp);

        const int idx = b * TM1 + tid;
        d_out[1 + idx]                = p * maskf;
        d_out[1 + NROW + idx]         = a * maskf;
        d_out[1 + 2 * NROW + idx]     = maskf;
    }

    __shared__ float s_f[256];
    s_f[tid] = bce * maskf;
    __syncthreads();
    #pragma unroll
    for (int off = 128; off > 0; off >>= 1) {
        if (tid < off) s_f[tid] += s_f[tid + off];
        __syncthreads();
    }
    if (tid == 0) g_lossb[b] = s_f[0] / cnt;
}

// ---------------------------------------------------------------------------
// Kernel 3: deterministic sum of the 64 per-b losses.
// ---------------------------------------------------------------------------
__global__ void final_sum_kernel(float* __restrict__ d_out)
{
    __shared__ float s[64];
    s[threadIdx.x] = g_lossb[threadIdx.x];
    __syncthreads();
    #pragma unroll
    for (int off = 32; off > 0; off >>= 1) {
        if (threadIdx.x < off) s[threadIdx.x] += s[threadIdx.x + off];
        __syncthreads();
    }
    if (threadIdx.x == 0) d_out[0] = s[0];
}

extern "C" void kernel_launch(void* const* d_in, const int* in_sizes, int n_in,
                              void* d_out, int out_size)
{
    const float* pred  = (const float*)d_in[0];
    const float* batch = (const float*)d_in[1];
    const int*   isT   = (const int*)d_in[2];
    const int*   tsl   = (const int*)d_in[3];
    float*       out   = (float*)d_out;

    scan_rows_kernel<<<NROW, 256>>>(pred, batch);
    per_batch_kernel<<<B, 256>>>(isT, tsl, out);
    final_sum_kernel<<<1, 64>>>(out);
}

// round 2
// speedup vs baseline: 1.4136x; 1.4136x over previous
#include <cuda_runtime.h>
#include <math.h>

#define B      64
#define T      200
#define Q      4096
#define Q2     (2*Q)
#define TM1    (T-1)          // 199
#define NROW   (B*TM1)        // 12736
#define NPROBE 12             // probe rows s = 16, 32, ..., 192

// Scratch (no device allocation allowed in kernel_launch)
__device__ float g_p[NROW];
__device__ float g_a[NROW];
__device__ int   g_flag[NROW];
__device__ int   g_probe[B * NPROBE];
__device__ float g_lossb[B];

// ---------------------------------------------------------------------------
// Block-cooperative scan of batch row (b, s): 8192 floats in 8 chunks of 1024,
// early exit via __syncthreads_or once the one-hot is found.
// Returns one-hot index in [0, 8192) or -1 (all threads get the same value).
// ---------------------------------------------------------------------------
__device__ __forceinline__ int scan_row(const float* __restrict__ batch,
                                        int b, int s)
{
    const float4* __restrict__ base =
        reinterpret_cast<const float4*>(batch + ((size_t)b * T + s) * (size_t)Q2);
    const int tid = threadIdx.x;

    __shared__ int s_idx;
    if (tid == 0) s_idx = -1;
    __syncthreads();

    #pragma unroll 1
    for (int c = 0; c < 8; ++c) {
        const int vi = c * 256 + tid;
        const float4 v = base[vi];
        int f = -1;
        if (v.x != 0.0f) f = vi * 4 + 0;
        if (v.y != 0.0f) f = vi * 4 + 1;
        if (v.z != 0.0f) f = vi * 4 + 2;
        if (v.w != 0.0f) f = vi * 4 + 3;
        if (f >= 0) s_idx = f;                 // at most one thread ever writes
        if (__syncthreads_or(f >= 0)) break;   // barrier orders store vs reads
    }
    return s_idx;                              // safe: last barrier ordered it
}

// Record p/a/flag for output row (b, t) given one-hot index j (or -1).
__device__ __forceinline__ void store_row(const float* __restrict__ pred,
                                          int b, int t, int j)
{
    if (threadIdx.x == 0) {
        float p = 0.0f, a = 0.0f;
        int fl = 0;
        if (j >= 0) {
            const int q = j & (Q - 1);         // j mod 4096
            a  = (j < Q) ? 1.0f : 0.0f;
            p  = __ldg(pred + ((size_t)b * T + t) * (size_t)Q + q);
            fl = 1;
        }
        const int row = b * TM1 + t;
        g_p[row]    = p;
        g_a[row]    = a;
        g_flag[row] = fl;
    }
}

// ---------------------------------------------------------------------------
// K1: probe rows s = 16k (k=1..12) per batch. Records probe validity AND the
// full result for those rows (so the main pass can skip them entirely).
// ---------------------------------------------------------------------------
__global__ __launch_bounds__(256)
void probe_kernel(const float* __restrict__ pred,
                  const float* __restrict__ batch)
{
    const int b = blockIdx.x / NPROBE;
    const int k = blockIdx.x % NPROBE;   // 0..11
    const int s = 16 * (k + 1);          // 16..192
    const int j = scan_row(batch, b, s);
    store_row(pred, b, s - 1, j);
    if (threadIdx.x == 0) g_probe[b * NPROBE + k] = (j >= 0) ? 1 : 0;
}

// ---------------------------------------------------------------------------
// K2: main scan. Rows known-invalid from the probes are zero-written with NO
// memory reads; probed rows are skipped (K1 wrote them); the rest scan with
// early exit.
// ---------------------------------------------------------------------------
__global__ __launch_bounds__(256)
void scan_kernel(const float* __restrict__ pred,
                 const float* __restrict__ batch)
{
    const int row = blockIdx.x;
    const int b   = row / TM1;
    const int t   = row % TM1;
    const int s   = t + 1;

    if (s <= 192 && (s & 15) == 0) return;   // handled by probe_kernel

    __shared__ int s_ub;
    if (threadIdx.x == 0) {
        int ub = 200;
        #pragma unroll
        for (int k = 0; k < NPROBE; ++k) {
            const int sk = 16 * (k + 1);
            if (!g_probe[b * NPROBE + k] && sk < ub) ub = sk;
        }
        s_ub = ub;
    }
    __syncthreads();

    if (s >= s_ub) {                 // provably all-zero row: no reads at all
        store_row(pred, b, t, -1);
        return;
    }
    const int j = scan_row(batch, b, s);
    store_row(pred, b, t, j);
}

// ---------------------------------------------------------------------------
// K3: one block per b. last/start/mask/cnt, BCE, the three output arrays,
// per-b partial loss.
// Output layout: [0]=loss, [1..1+N)=p*maskf, [1+N..1+2N)=a*maskf,
//                [1+2N..1+3N)=mask, N = B*TM1.
// ---------------------------------------------------------------------------
__global__ __launch_bounds__(256)
void per_batch_kernel(const int* __restrict__ isTestP,
                      const int* __restrict__ tslP,
                      float* __restrict__ d_out)
{
    const int b   = blockIdx.x;
    const int tid = threadIdx.x;

    float p = 0.0f, a = 0.0f;
    int myLast = -1;
    if (tid < TM1) {
        const int idx = b * TM1 + tid;
        p = g_p[idx];
        a = g_a[idx];
        if (g_flag[idx] > 0) myLast = tid;
    }

    __shared__ int s_i[256];
    s_i[tid] = myLast;
    __syncthreads();
    #pragma unroll
    for (int off = 128; off > 0; off >>= 1) {
        if (tid < off) s_i[tid] = max(s_i[tid], s_i[tid + off]);
        __syncthreads();
    }
    const int last = max(s_i[0], 0);

    int start = 0;
    if (*isTestP) {
        const int length = last + 1;
        const int tsl = *tslP;
        start = (length > tsl) ? (length - tsl) : 0;
    }

    const bool  m     = (tid < TM1) && (tid >= start) && (tid <= last);
    const float maskf = m ? 1.0f : 0.0f;
    const float cnt   = (float)(last - start + 1);

    float bce = 0.0f;
    if (tid < TM1) {
        const float logp = fmaxf(logf(p), -100.0f);
        const float l1mp = fmaxf(log1pf(-p), -100.0f);
        bce = -(a * logp + (1.0f - a) * l1mp);

        const int idx = b * TM1 + tid;
        d_out[1 + idx]            = p * maskf;
        d_out[1 + NROW + idx]     = a * maskf;
        d_out[1 + 2 * NROW + idx] = maskf;
    }

    __shared__ float s_f[256];
    s_f[tid] = bce * maskf;
    __syncthreads();
    #pragma unroll
    for (int off = 128; off > 0; off >>= 1) {
        if (tid < off) s_f[tid] += s_f[tid + off];
        __syncthreads();
    }
    if (tid == 0) g_lossb[b] = s_f[0] / cnt;
}

__global__ void final_sum_kernel(float* __restrict__ d_out)
{
    __shared__ float s[64];
    s[threadIdx.x] = g_lossb[threadIdx.x];
    __syncthreads();
    #pragma unroll
    for (int off = 32; off > 0; off >>= 1) {
        if (threadIdx.x < off) s[threadIdx.x] += s[threadIdx.x + off];
        __syncthreads();
    }
    if (threadIdx.x == 0) d_out[0] = s[0];
}

extern "C" void kernel_launch(void* const* d_in, const int* in_sizes, int n_in,
                              void* d_out, int out_size)
{
    const float* pred  = (const float*)d_in[0];
    const float* batch = (const float*)d_in[1];
    const int*   isT   = (const int*)d_in[2];
    const int*   tsl   = (const int*)d_in[3];
    float*       out   = (float*)d_out;

    probe_kernel<<<B * NPROBE, 256>>>(pred, batch);
    scan_kernel<<<NROW, 256>>>(pred, batch);
    per_batch_kernel<<<B, 256>>>(isT, tsl, out);
    final_sum_kernel<<<1, 64>>>(out);
}

// round 3
// speedup vs baseline: 1.4761x; 1.0442x over previous
#include <cuda_runtime.h>
#include <math.h>

#define B      64
#define T      200
#define Q      4096
#define Q2     (2*Q)
#define TM1    (T-1)          // 199
#define NROW   (B*TM1)        // 12736
#define NPROBE 12             // probe rows s = 16, 32, ..., 192

// Scratch (no device allocation allowed in kernel_launch)
__device__ float g_p[NROW];
__device__ float g_a[NROW];
__device__ int   g_flag[NROW];
__device__ int   g_probe[B * NPROBE];
__device__ float g_lossb[B];
__device__ int   g_count;      // zero-initialized; self-resets each replay

// ---------------------------------------------------------------------------
// Block-cooperative scan of batch row (b, s) with software pipelining:
// the load for chunk c+1 is issued BEFORE the barrier that decides early exit
// on chunk c, so the barrier wait covers an in-flight load instead of a
// fresh DRAM round-trip. Over-reads at most one 4 KB chunk.
// Returns one-hot index in [0, 8192) or -1 (uniform across the block).
// ---------------------------------------------------------------------------
__device__ __forceinline__ int scan_row(const float* __restrict__ batch,
                                        int b, int s)
{
    const float4* __restrict__ base =
        reinterpret_cast<const float4*>(batch + ((size_t)b * T + s) * (size_t)Q2);
    const int tid = threadIdx.x;

    __shared__ int s_idx;
    if (tid == 0) s_idx = -1;
    __syncthreads();

    float4 cur = base[tid];                      // chunk 0 in flight early
    #pragma unroll 1
    for (int c = 0; c < 8; ++c) {
        float4 nxt = make_float4(0.f, 0.f, 0.f, 0.f);
        if (c < 7) nxt = base[(c + 1) * 256 + tid];   // prefetch chunk c+1

        const int vi = c * 256 + tid;
        int f = -1;
        if (cur.x != 0.0f) f = vi * 4 + 0;
        if (cur.y != 0.0f) f = vi * 4 + 1;
        if (cur.z != 0.0f) f = vi * 4 + 2;
        if (cur.w != 0.0f) f = vi * 4 + 3;
        if (f >= 0) s_idx = f;                   // at most one thread writes
        if (__syncthreads_or(f >= 0)) break;     // barrier orders store/read
        cur = nxt;
    }
    return s_idx;
}

// Record p/a/flag for output row (b, t) given one-hot index j (or -1).
__device__ __forceinline__ void store_row(const float* __restrict__ pred,
                                          int b, int t, int j)
{
    if (threadIdx.x == 0) {
        float p = 0.0f, a = 0.0f;
        int fl = 0;
        if (j >= 0) {
            const int q = j & (Q - 1);
            a  = (j < Q) ? 1.0f : 0.0f;
            p  = __ldg(pred + ((size_t)b * T + t) * (size_t)Q + q);
            fl = 1;
        }
        const int row = b * TM1 + t;
        g_p[row]    = p;
        g_a[row]    = a;
        g_flag[row] = fl;
    }
}

// ---------------------------------------------------------------------------
// K1: probe rows s = 16k (k=1..12) per batch; records validity and the full
// result for those rows.
// ---------------------------------------------------------------------------
__global__ __launch_bounds__(256)
void probe_kernel(const float* __restrict__ pred,
                  const float* __restrict__ batch)
{
    const int b = blockIdx.x / NPROBE;
    const int k = blockIdx.x % NPROBE;
    const int s = 16 * (k + 1);
    const int j = scan_row(batch, b, s);
    store_row(pred, b, s - 1, j);
    if (threadIdx.x == 0) g_probe[b * NPROBE + k] = (j >= 0) ? 1 : 0;
}

// ---------------------------------------------------------------------------
// K2: main scan. Probed rows skipped; rows provably past the boundary are
// zero-written with no reads; the rest scan pipelined with early exit.
// ---------------------------------------------------------------------------
__global__ __launch_bounds__(256)
void scan_kernel(const float* __restrict__ pred,
                 const float* __restrict__ batch)
{
    const int row = blockIdx.x;
    const int b   = row / TM1;
    const int t   = row % TM1;
    const int s   = t + 1;

    if (s <= 192 && (s & 15) == 0) return;       // handled by probe_kernel

    __shared__ int s_ub;
    if (threadIdx.x == 0) {
        int ub = 200;
        #pragma unroll
        for (int k = 0; k < NPROBE; ++k) {
            const int sk = 16 * (k + 1);
            if (!g_probe[b * NPROBE + k] && sk < ub) ub = sk;
        }
        s_ub = ub;
    }
    __syncthreads();

    if (s >= s_ub) {                             // provably all-zero row
        store_row(pred, b, t, -1);
        return;
    }
    const int j = scan_row(batch, b, s);
    store_row(pred, b, t, j);
}

// ---------------------------------------------------------------------------
// K3: merged epilogue. Block b: last/start/mask/cnt, BCE, output arrays,
// per-b loss. The last block to finish does the deterministic 64-way sum
// (fixed tree order) and resets the counter for the next graph replay.
// Output layout: [0]=loss, [1..1+N)=p*maskf, [1+N..1+2N)=a*maskf,
//                [1+2N..1+3N)=mask, N = B*TM1.
// ---------------------------------------------------------------------------
__global__ __launch_bounds__(256)
void epilogue_kernel(const int* __restrict__ isTestP,
                     const int* __restrict__ tslP,
                     float* __restrict__ d_out)
{
    const int b   = blockIdx.x;
    const int tid = threadIdx.x;

    float p = 0.0f, a = 0.0f;
    int myLast = -1;
    if (tid < TM1) {
        const int idx = b * TM1 + tid;
        p = g_p[idx];
        a = g_a[idx];
        if (g_flag[idx] > 0) myLast = tid;
    }

    __shared__ int s_i[256];
    s_i[tid] = myLast;
    __syncthreads();
    #pragma unroll
    for (int off = 128; off > 0; off >>= 1) {
        if (tid < off) s_i[tid] = max(s_i[tid], s_i[tid + off]);
        __syncthreads();
    }
    const int last = max(s_i[0], 0);

    int start = 0;
    if (*isTestP) {
        const int length = last + 1;
        const int tsl = *tslP;
        start = (length > tsl) ? (length - tsl) : 0;
    }

    const bool  m     = (tid < TM1) && (tid >= start) && (tid <= last);
    const float maskf = m ? 1.0f : 0.0f;
    const float cnt   = (float)(last - start + 1);

    float bce = 0.0f;
    if (tid < TM1) {
        const float logp = fmaxf(logf(p), -100.0f);
        const float l1mp = fmaxf(log1pf(-p), -100.0f);
        bce = -(a * logp + (1.0f - a) * l1mp);

        const int idx = b * TM1 + tid;
        d_out[1 + idx]            = p * maskf;
        d_out[1 + NROW + idx]     = a * maskf;
        d_out[1 + 2 * NROW + idx] = maskf;
    }

    __shared__ float s_f[256];
    s_f[tid] = bce * maskf;
    __syncthreads();
    #pragma unroll
    for (int off = 128; off > 0; off >>= 1) {
        if (tid < off) s_f[tid] += s_f[tid + off];
        __syncthreads();
    }

    __shared__ bool s_last;
    if (tid == 0) {
        g_lossb[b] = s_f[0] / cnt;
        __threadfence();
        s_last = (atomicAdd(&g_count, 1) == B - 1);
    }
    __syncthreads();

    if (s_last) {                                // deterministic final sum
        __shared__ float s2[64];
        if (tid < B) s2[tid] = g_lossb[tid];
        __syncthreads();
        #pragma unroll
        for (int off = 32; off > 0; off >>= 1) {
            if (tid < off) s2[tid] += s2[tid + off];
            __syncthreads();
        }
        if (tid == 0) {
            d_out[0] = s2[0];
            g_count  = 0;                        // reset for next replay
        }
    }
}

extern "C" void kernel_launch(void* const* d_in, const int* in_sizes, int n_in,
                              void* d_out, int out_size)
{
    const float* pred  = (const float*)d_in[0];
    const float* batch = (const float*)d_in[1];
    const int*   isT   = (const int*)d_in[2];
    const int*   tsl   = (const int*)d_in[3];
    float*       out   = (float*)d_out;

    probe_kernel<<<B * NPROBE, 256>>>(pred, batch);
    scan_kernel<<<NROW, 256>>>(pred, batch);
    epilogue_kernel<<<B, 256>>>(isT, tsl, out);
}